// round 13
// baseline (speedup 1.0000x reference)
#include <cuda_runtime.h>
#include <cstdint>

#define BB 256
#define TT 1024
#define EE 32
#define HH 64
#define GG 256          // 4*H
#define VV 96
#define NROWS (BB*TT)   // 262144
#define NLOGITS (NROWS*VV)

typedef unsigned long long u64;

// ---------------- scratch (device globals: no allocation allowed) ----------
// Thread j (0..127): w=j>>5, l=j&31, m=l&15, sel=(l>>4)&1, u=16*w+m.
//   sel=0: gate rows (i[u], g[u])  = (u,     128+u)
//   sel=1: gate rows (f[u], o[u])  = (64+u,  192+u)
__device__ float2 g_projP[VV][128];   // paired (W_ih@emb[v] + b_ih + b_hh): (row_a, row_b)
// k-paired weights: g_W2[j][k], k<32: (W[ra][2k],W[ra][2k+1]); k>=32: row rb pairs
__device__ float2 g_W2[128][HH];
__device__ float  g_hseq[(size_t)NROWS * HH];     // 64 MB hidden-state sequence
__device__ double g_loss;
__device__ unsigned g_cnt;

// ---------------- f32x2 helpers -------------------------------------------
__device__ __forceinline__ void ffma2(u64 &d, u64 a, u64 b) {
    asm("fma.rn.f32x2 %0, %1, %2, %0;" : "+l"(d) : "l"(a), "l"(b));
}
__device__ __forceinline__ u64 fadd2(u64 a, u64 b) {
    u64 d; asm("add.rn.f32x2 %0, %1, %2;" : "=l"(d) : "l"(a), "l"(b)); return d;
}
__device__ __forceinline__ u64 f2_dup(float x) {
    u64 r; asm("mov.b64 %0, {%1, %1};" : "=l"(r) : "f"(x)); return r;
}
__device__ __forceinline__ u64 f2_lo(float x) {  // (x, 0)
    u64 r; asm("mov.b64 %0, {%1, %2};" : "=l"(r) : "f"(x), "f"(0.f)); return r;
}
__device__ __forceinline__ void f2_unpack(u64 v, float &a, float &b) {
    asm("mov.b64 {%0, %1}, %2;" : "=f"(a), "=f"(b) : "l"(v));
}

// fast tanh via MUFU.TANH (measured rel_err 1.8e-6 in this regime)
__device__ __forceinline__ float tanh_f(float x) {
    float r; asm("tanh.approx.f32 %0, %1;" : "=f"(r) : "f"(x)); return r;
}

// thread j -> paired gate rows
__device__ __host__ __forceinline__ void rows_of(int j, int &ra, int &rb) {
    int w = j >> 5, l = j & 31, m = l & 15, sel = (l >> 4) & 1;
    int u = 16 * w + m;
    ra = 64 * sel + u;
    rb = ra + 128;
}

// ---------------- kernel 1: prep ------------------------------------------
// Blocks 0..95: proj table row for vocab v = blockIdx (W_ih/emb staged in smem,
// coalesced). All blocks also cover the weight repack (8192 float2 spread).
__global__ __launch_bounds__(128) void prep_kernel(const float* __restrict__ emb,
                            const float* __restrict__ W_ih,
                            const float* __restrict__ W_hh, const float* __restrict__ b_ih,
                            const float* __restrict__ b_hh)
{
    __shared__ float sW[GG * EE];                 // 32 KB: full W_ih
    __shared__ float sE[EE];                      // emb row v
    __shared__ float sB[GG];                      // b_ih + b_hh

    int tid = threadIdx.x;
    int v   = blockIdx.x;

    // distributed weight repack: element i = 128*bid + tid
    {
        int i = blockIdx.x * 128 + tid;
        if (i < 128 * HH) {
            int j = i >> 6, k = i & 63;
            int ra, rb; rows_of(j, ra, rb);
            int row = (k < 32) ? ra : rb;
            int kk  = (k < 32) ? k : (k - 32);
            g_W2[j][k] = make_float2(W_hh[row * HH + 2 * kk], W_hh[row * HH + 2 * kk + 1]);
        }
        if (blockIdx.x == 0 && tid == 0) { g_loss = 0.0; g_cnt = 0u; }
    }

    // stage W_ih (coalesced), emb row, biases
    for (int i = tid; i < GG * EE; i += 128) sW[i] = W_ih[i];
    if (tid < EE) sE[tid] = emb[v * EE + tid];
    for (int i = tid; i < GG; i += 128) sB[i] = b_ih[i] + b_hh[i];
    __syncthreads();

    int j = tid;
    int ra, rb; rows_of(j, ra, rb);
    float sa = sB[ra];
    float sb = sB[rb];
    #pragma unroll
    for (int e = 0; e < EE; e++) {
        float ev = sE[e];
        sa += sW[ra * EE + e] * ev;
        sb += sW[rb * EE + e] * ev;
    }
    g_projP[v][j] = make_float2(sa, sb);
}

// ---------------- kernel 2: LSTM scan (critical path) ----------------------
// R12 core (proven 421.7us) + tail trims: xp folded into chain inits, hout
// STG moved past the barrier, pointer-increment hout.
__global__ __launch_bounds__(128) void lstm_kernel(const int* __restrict__ idx)
{
    __shared__ __align__(16) float sh_h[2][HH];   // double-buffered h (single copy)
    __shared__ __align__(16) int sh_idx[TT + 4];  // +sentinel (single row, aligned)

    int j = threadIdx.x;                          // 0..127
    int l = j & 31, m = l & 15, sel = (l >> 4) & 1;
    int u = 16 * (j >> 5) + m;
    int b = blockIdx.x;

    // stage idx row in smem (coalesced, once)
    {
        const int4* src = (const int4*)(idx + (size_t)b * TT);
        int4* dst = (int4*)sh_idx;
        #pragma unroll
        for (int i = j; i < TT / 4; i += 128) dst[i] = src[i];
    }

    // weights into registers (64 x u64 = 128 regs): w[0..31]=row ra, w[32..63]=row rb
    u64 w[HH];
    {
        const u64* wp = (const u64*)g_W2[j];
        #pragma unroll
        for (int k = 0; k < HH; k++) w[k] = wp[k];
    }
    if (j < HH) sh_h[0][j] = 0.f;
    if (j == 0) sh_idx[TT] = 0;                   // sentinel (any valid vocab id)

    float cst = 0.f;                              // cell state (sel=1 lanes)
    // act1: sigma(x) = 0.5 + 0.5*tanh(0.5x) (i or f)
    // act2: sel=0 -> tanh(g): S=1,A=1,D=0 ; sel=1 -> sigma(o): S=A=D=0.5
    float Sg = sel ? 0.5f : 1.0f;
    float Ag = sel ? 0.5f : 1.0f;
    float Dg = sel ? 0.5f : 0.0f;
    float* hout = g_hseq + (size_t)b * TT * HH + u;

    __syncthreads();

    float2 xp = g_projP[sh_idx[0]][j];            // (xp_ra, xp_rb)

    for (int t = 0; t < TT; t++) {
        float2 xp_pf = g_projP[sh_idx[t + 1]][j]; // L2-resident prefetch

        // 4 chains: (a0,a1) row ra, (b0,b1) row rb; xp folded into inits
        u64 a0 = f2_lo(xp.x), a1 = 0ull, b0 = f2_lo(xp.y), b1 = 0ull;
        const ulonglong2* h4 = (const ulonglong2*)sh_h[t & 1];
        #pragma unroll
        for (int kk = 0; kk < 16; kk++) {
            ulonglong2 hh = h4[kk];               // LDS.128: h[4kk..4kk+3]
            ffma2(a0, hh.x, w[2 * kk]);
            ffma2(b0, hh.x, w[32 + 2 * kk]);
            ffma2(a1, hh.y, w[2 * kk + 1]);
            ffma2(b1, hh.y, w[32 + 2 * kk + 1]);
        }
        u64 sa = fadd2(a0, a1);
        u64 sb = fadd2(b0, b1);
        float sa0, sa1, sb0, sb1;
        f2_unpack(sa, sa0, sa1);
        f2_unpack(sb, sb0, sb1);
        float glo = sa0 + sa1;                    // gate row ra pre-activation
        float ghi = sb0 + sb1;                    // gate row rb pre-activation

        float fi = fmaf(0.5f, tanh_f(0.5f * glo), 0.5f);    // sigm: i / f
        float go = fmaf(Ag, tanh_f(Sg * ghi), Dg);          // tanh(g) / sigm(o)

        float p  = fi * go;                                 // sigm(i)*tanh(g) on sel=0
        float pr = __shfl_up_sync(0xffffffffu, p, 16);

        float h = 0.f;
        if (sel) {
            cst = fmaf(fi, cst, pr);                        // c = f*c + i*g
            h = go * tanh_f(cst);                           // h = o*tanh(c)
            sh_h[(t + 1) & 1][u] = h;                       // pre-barrier: smem only
        }
        __syncthreads();
        if (sel) hout[0] = h;                               // STG off the critical tail
        hout += HH;
        xp = xp_pf;
    }
}

// ---------------- kernel 3: output projection + log-softmax + loss ---------
__global__ __launch_bounds__(256) void outproj_kernel(const float* __restrict__ fc_w,
                                                      const float* __restrict__ fc_b,
                                                      const int*   __restrict__ targets,
                                                      float*       __restrict__ out,
                                                      int          write_loss)
{
    __shared__ float wS[HH][97];                  // wS[k][v] = fc_w[v][k]
    __shared__ __align__(16) float hS[HH][66];    // hS[k][r]
    __shared__ float bS[VV];

    int tid = threadIdx.x;
    for (int i = tid; i < VV * HH; i += 256) { int v = i >> 6, k = i & 63; wS[k][v] = fc_w[i]; }
    if (tid < VV) bS[tid] = fc_b[tid];

    int rbase = blockIdx.x * 64;
    for (int i4 = tid; i4 < 64 * 16; i4 += 256) {
        int r = i4 >> 4, k4 = (i4 & 15) << 2;
        float4 hv = *(const float4*)&g_hseq[((size_t)(rbase + r)) * HH + k4];
        hS[k4][r] = hv.x; hS[k4 + 1][r] = hv.y; hS[k4 + 2][r] = hv.z; hS[k4 + 3][r] = hv.w;
    }
    __syncthreads();

    int tc = tid & 31, tr = tid >> 5;
    int c0 = 3 * tc;

    u64 acc[4][3];
    #pragma unroll
    for (int p = 0; p < 4; p++)
        #pragma unroll
        for (int q = 0; q < 3; q++) acc[p][q] = 0ull;

    #pragma unroll 4
    for (int k = 0; k < HH; k++) {
        u64 b0 = f2_dup(wS[k][c0]);
        u64 b1 = f2_dup(wS[k][c0 + 1]);
        u64 b2 = f2_dup(wS[k][c0 + 2]);
        #pragma unroll
        for (int p = 0; p < 4; p++) {
            u64 a = *(const u64*)&hS[k][(tr * 4 + p) * 2];
            ffma2(acc[p][0], a, b0);
            ffma2(acc[p][1], a, b1);
            ffma2(acc[p][2], a, b2);
        }
    }

    float lg[8][3];
    #pragma unroll
    for (int p = 0; p < 4; p++)
        #pragma unroll
        for (int q = 0; q < 3; q++) {
            float lo, hi; f2_unpack(acc[p][q], lo, hi);
            lg[2 * p][q]     = lo + bS[c0 + q];
            lg[2 * p + 1][q] = hi + bS[c0 + q];
        }

    float lacc = 0.f;
    #pragma unroll
    for (int rr = 0; rr < 8; rr++) {
        int row = tr * 8 + rr;
        float v0 = lg[rr][0], v1 = lg[rr][1], v2 = lg[rr][2];
        float* gout = out + (size_t)(rbase + row) * VV + c0;
        gout[0] = v0; gout[1] = v1; gout[2] = v2;

        float mx = fmaxf(v0, fmaxf(v1, v2));
        #pragma unroll
        for (int off = 16; off; off >>= 1) mx = fmaxf(mx, __shfl_xor_sync(0xffffffffu, mx, off));
        float s = __expf(v0 - mx) + __expf(v1 - mx) + __expf(v2 - mx);
        #pragma unroll
        for (int off = 16; off; off >>= 1) s += __shfl_xor_sync(0xffffffffu, s, off);

        int tgt = targets[rbase + row];
        bool own = (tgt >= c0) && (tgt < c0 + 3);
        float lt = (tgt == c0) ? v0 : ((tgt == c0 + 1) ? v1 : v2);
        lacc += own ? (mx + __logf(s) - lt) : 0.f;
    }
    #pragma unroll
    for (int off = 16; off; off >>= 1) lacc += __shfl_xor_sync(0xffffffffu, lacc, off);
    if (tc == 0) atomicAdd(&g_loss, (double)lacc);

    // last finished block writes the mean loss (no extra kernel launch)
    if (write_loss) {
        __syncthreads();
        if (tid == 0) {
            __threadfence();
            unsigned old = atomicAdd(&g_cnt, 1u);
            if (old == gridDim.x - 1) {
                __threadfence();
                out[NLOGITS] = (float)(g_loss * (1.0 / (double)NROWS));
            }
        }
    }
}

// ---------------- launch ----------------------------------------------------
extern "C" void kernel_launch(void* const* d_in, const int* in_sizes, int n_in,
                              void* d_out, int out_size)
{
    const int*   idx     = (const int*)  d_in[0];
    const int*   targets = (const int*)  d_in[1];
    const float* emb     = (const float*)d_in[2];
    const float* W_ih    = (const float*)d_in[3];
    const float* W_hh    = (const float*)d_in[4];
    const float* b_ih    = (const float*)d_in[5];
    const float* b_hh    = (const float*)d_in[6];
    const float* fc_w    = (const float*)d_in[7];
    const float* fc_b    = (const float*)d_in[8];
    float* out = (float*)d_out;

    int write_loss = (out_size > NLOGITS) ? 1 : 0;

    prep_kernel<<<VV, 128>>>(emb, W_ih, W_hh, b_ih, b_hh);
    lstm_kernel<<<BB, 128>>>(idx);
    outproj_kernel<<<NROWS / 64, 256>>>(fc_w, fc_b, targets, out, write_loss);
}

// round 14
// speedup vs baseline: 1.0243x; 1.0243x over previous
#include <cuda_runtime.h>
#include <cstdint>

#define BB 256
#define TT 1024
#define EE 32
#define HH 64
#define GG 256          // 4*H
#define VV 96
#define NROWS (BB*TT)   // 262144
#define NLOGITS (NROWS*VV)

typedef unsigned long long u64;

// ---------------- scratch (device globals: no allocation allowed) ----------
// Thread j (0..127): w=j>>5, l=j&31, m=l&15, sel=(l>>4)&1, u=16*w+m.
//   sel=0: gate rows (i[u], g[u])  = (u,     128+u)
//   sel=1: gate rows (f[u], o[u])  = (64+u,  192+u)
__device__ float2 g_projP[VV][128];   // paired (W_ih@emb[v] + b_ih + b_hh): (row_a, row_b)
// k-paired weights: g_W2[j][k], k<32: (W[ra][2k],W[ra][2k+1]); k>=32: row rb pairs
__device__ float2 g_W2[128][HH];
__device__ float  g_hseq[(size_t)NROWS * HH];     // 64 MB hidden-state sequence
__device__ double g_loss;
__device__ unsigned g_cnt;

// ---------------- f32x2 helpers -------------------------------------------
__device__ __forceinline__ void ffma2(u64 &d, u64 a, u64 b) {
    asm("fma.rn.f32x2 %0, %1, %2, %0;" : "+l"(d) : "l"(a), "l"(b));
}
__device__ __forceinline__ u64 fadd2(u64 a, u64 b) {
    u64 d; asm("add.rn.f32x2 %0, %1, %2;" : "=l"(d) : "l"(a), "l"(b)); return d;
}
__device__ __forceinline__ u64 f2_dup(float x) {
    u64 r; asm("mov.b64 %0, {%1, %1};" : "=l"(r) : "f"(x)); return r;
}
__device__ __forceinline__ void f2_unpack(u64 v, float &a, float &b) {
    asm("mov.b64 {%0, %1}, %2;" : "=f"(a), "=f"(b) : "l"(v));
}

// fast tanh via MUFU.TANH (measured rel_err 1.8e-6 in this regime)
__device__ __forceinline__ float tanh_f(float x) {
    float r; asm("tanh.approx.f32 %0, %1;" : "=f"(r) : "f"(x)); return r;
}

// thread j -> paired gate rows
__device__ __host__ __forceinline__ void rows_of(int j, int &ra, int &rb) {
    int w = j >> 5, l = j & 31, m = l & 15, sel = (l >> 4) & 1;
    int u = 16 * w + m;
    ra = 64 * sel + u;
    rb = ra + 128;
}

// ---------------- kernel 1: prep ------------------------------------------
__global__ __launch_bounds__(128) void prep_kernel(const float* __restrict__ emb,
                            const float* __restrict__ W_ih,
                            const float* __restrict__ W_hh, const float* __restrict__ b_ih,
                            const float* __restrict__ b_hh)
{
    __shared__ float sW[GG * EE];                 // 32 KB: full W_ih
    __shared__ float sE[EE];                      // emb row v
    __shared__ float sB[GG];                      // b_ih + b_hh

    int tid = threadIdx.x;
    int v   = blockIdx.x;

    // distributed weight repack: element i = 128*bid + tid
    {
        int i = blockIdx.x * 128 + tid;
        if (i < 128 * HH) {
            int j = i >> 6, k = i & 63;
            int ra, rb; rows_of(j, ra, rb);
            int row = (k < 32) ? ra : rb;
            int kk  = (k < 32) ? k : (k - 32);
            g_W2[j][k] = make_float2(W_hh[row * HH + 2 * kk], W_hh[row * HH + 2 * kk + 1]);
        }
        if (blockIdx.x == 0 && tid == 0) { g_loss = 0.0; g_cnt = 0u; }
    }

    for (int i = tid; i < GG * EE; i += 128) sW[i] = W_ih[i];
    if (tid < EE) sE[tid] = emb[v * EE + tid];
    for (int i = tid; i < GG; i += 128) sB[i] = b_ih[i] + b_hh[i];
    __syncthreads();

    int j = tid;
    int ra, rb; rows_of(j, ra, rb);
    float sa = sB[ra];
    float sb = sB[rb];
    #pragma unroll
    for (int e = 0; e < EE; e++) {
        float ev = sE[e];
        sa += sW[ra * EE + e] * ev;
        sb += sW[rb * EE + e] * ev;
    }
    g_projP[v][j] = make_float2(sa, sb);
}

// ---------------- kernel 2: LSTM scan (critical path) ----------------------
// EXACT R12 core (proven 421.7us) + ONE addition: blocks >=148 (co-resident
// CLC partners of blocks 0..107) run a one-time ~384-cycle dependent-FMA delay
// so the SM's two blocks execute antiphase, mutually hiding the ~160-cycle
// serial activation/update tail that barrier-synced warps expose every step.
__global__ __launch_bounds__(128) void lstm_kernel(const int* __restrict__ idx)
{
    __shared__ __align__(16) float sh_h[2][HH];   // double-buffered h (single copy)
    __shared__ __align__(16) int sh_idx[TT + 4];  // +sentinel (single row, aligned)

    int j = threadIdx.x;                          // 0..127
    int l = j & 31, m = l & 15, sel = (l >> 4) & 1;
    int u = 16 * (j >> 5) + m;
    int b = blockIdx.x;

    // stage idx row in smem (coalesced, once)
    {
        const int4* src = (const int4*)(idx + (size_t)b * TT);
        int4* dst = (int4*)sh_idx;
        #pragma unroll
        for (int i = j; i < TT / 4; i += 128) dst[i] = src[i];
    }

    // weights into registers (64 x u64 = 128 regs): w[0..31]=row ra, w[32..63]=row rb
    u64 w[HH];
    {
        const u64* wp = (const u64*)g_W2[j];
        #pragma unroll
        for (int k = 0; k < HH; k++) w[k] = wp[k];
    }
    if (j < HH) sh_h[0][j] = 0.f;
    if (j == 0) sh_idx[TT] = 0;                   // sentinel (any valid vocab id)

    float cst = 0.f;                              // cell state (sel=1 lanes)
    // act1: sigma(x) = 0.5 + 0.5*tanh(0.5x) (i or f)
    // act2: sel=0 -> tanh(g): S=1,A=1,D=0 ; sel=1 -> sigma(o): S=A=D=0.5
    float Sg = sel ? 0.5f : 1.0f;
    float Ag = sel ? 0.5f : 1.0f;
    float Dg = sel ? 0.5f : 0.0f;
    float* hout = g_hseq + (size_t)b * TT * HH + u;

    // antiphase stagger: ~384-cycle dependent-FMA delay, no memory side
    // effects; z converges to ~1e4 so the compare is always false and cst
    // stays exactly 0 (deterministic).
    if (b >= 148) {
        float z = (float)(j + 1);
        #pragma unroll
        for (int i = 0; i < 96; i++) z = fmaf(z, 0.9999f, 1.0f);
        cst = (z > 1e30f) ? 1.0f : 0.0f;          // always 0; keeps chain live
    }

    __syncthreads();

    float2 xp = g_projP[sh_idx[0]][j];            // (xp_ra, xp_rb)

    for (int t = 0; t < TT; t++) {
        float2 xp_pf = g_projP[sh_idx[t + 1]][j]; // L2-resident prefetch

        // 4 chains: (a0,a1) row ra, (b0,b1) row rb; h pairs shared between rows
        u64 a0 = 0ull, a1 = 0ull, b0 = 0ull, b1 = 0ull;
        const ulonglong2* h4 = (const ulonglong2*)sh_h[t & 1];
        #pragma unroll
        for (int kk = 0; kk < 16; kk++) {
            ulonglong2 hh = h4[kk];               // LDS.128: h[4kk..4kk+3]
            ffma2(a0, hh.x, w[2 * kk]);
            ffma2(b0, hh.x, w[32 + 2 * kk]);
            ffma2(a1, hh.y, w[2 * kk + 1]);
            ffma2(b1, hh.y, w[32 + 2 * kk + 1]);
        }
        u64 sa = fadd2(a0, a1);
        u64 sb = fadd2(b0, b1);
        float sa0, sa1, sb0, sb1;
        f2_unpack(sa, sa0, sa1);
        f2_unpack(sb, sb0, sb1);
        float glo = (sa0 + sa1) + xp.x;           // gate row ra pre-activation
        float ghi = (sb0 + sb1) + xp.y;           // gate row rb pre-activation

        float fi = fmaf(0.5f, tanh_f(0.5f * glo), 0.5f);    // sigm: i / f
        float go = fmaf(Ag, tanh_f(Sg * ghi), Dg);          // tanh(g) / sigm(o)

        float p  = fi * go;                                 // sigm(i)*tanh(g) on sel=0
        float pr = __shfl_up_sync(0xffffffffu, p, 16);

        if (sel) {
            cst = fmaf(fi, cst, pr);                        // c = f*c + i*g
            float h = go * tanh_f(cst);                     // h = o*tanh(c)
            sh_h[(t + 1) & 1][u] = h;
            hout[(size_t)t * HH] = h;                       // coalesced 256B/step
        }
        __syncthreads();
        xp = xp_pf;
    }
}

// ---------------- kernel 3: output projection + log-softmax + loss ---------
__global__ __launch_bounds__(256) void outproj_kernel(const float* __restrict__ fc_w,
                                                      const float* __restrict__ fc_b,
                                                      const int*   __restrict__ targets,
                                                      float*       __restrict__ out,
                                                      int          write_loss)
{
    __shared__ float wS[HH][97];                  // wS[k][v] = fc_w[v][k]
    __shared__ __align__(16) float hS[HH][66];    // hS[k][r]
    __shared__ float bS[VV];

    int tid = threadIdx.x;
    for (int i = tid; i < VV * HH; i += 256) { int v = i >> 6, k = i & 63; wS[k][v] = fc_w[i]; }
    if (tid < VV) bS[tid] = fc_b[tid];

    int rbase = blockIdx.x * 64;
    for (int i4 = tid; i4 < 64 * 16; i4 += 256) {
        int r = i4 >> 4, k4 = (i4 & 15) << 2;
        float4 hv = *(const float4*)&g_hseq[((size_t)(rbase + r)) * HH + k4];
        hS[k4][r] = hv.x; hS[k4 + 1][r] = hv.y; hS[k4 + 2][r] = hv.z; hS[k4 + 3][r] = hv.w;
    }
    __syncthreads();

    int tc = tid & 31, tr = tid >> 5;
    int c0 = 3 * tc;

    u64 acc[4][3];
    #pragma unroll
    for (int p = 0; p < 4; p++)
        #pragma unroll
        for (int q = 0; q < 3; q++) acc[p][q] = 0ull;

    #pragma unroll 4
    for (int k = 0; k < HH; k++) {
        u64 b0 = f2_dup(wS[k][c0]);
        u64 b1 = f2_dup(wS[k][c0 + 1]);
        u64 b2 = f2_dup(wS[k][c0 + 2]);
        #pragma unroll
        for (int p = 0; p < 4; p++) {
            u64 a = *(const u64*)&hS[k][(tr * 4 + p) * 2];
            ffma2(acc[p][0], a, b0);
            ffma2(acc[p][1], a, b1);
            ffma2(acc[p][2], a, b2);
        }
    }

    float lg[8][3];
    #pragma unroll
    for (int p = 0; p < 4; p++)
        #pragma unroll
        for (int q = 0; q < 3; q++) {
            float lo, hi; f2_unpack(acc[p][q], lo, hi);
            lg[2 * p][q]     = lo + bS[c0 + q];
            lg[2 * p + 1][q] = hi + bS[c0 + q];
        }

    float lacc = 0.f;
    #pragma unroll
    for (int rr = 0; rr < 8; rr++) {
        int row = tr * 8 + rr;
        float v0 = lg[rr][0], v1 = lg[rr][1], v2 = lg[rr][2];
        float* gout = out + (size_t)(rbase + row) * VV + c0;
        gout[0] = v0; gout[1] = v1; gout[2] = v2;

        float mx = fmaxf(v0, fmaxf(v1, v2));
        #pragma unroll
        for (int off = 16; off; off >>= 1) mx = fmaxf(mx, __shfl_xor_sync(0xffffffffu, mx, off));
        float s = __expf(v0 - mx) + __expf(v1 - mx) + __expf(v2 - mx);
        #pragma unroll
        for (int off = 16; off; off >>= 1) s += __shfl_xor_sync(0xffffffffu, s, off);

        int tgt = targets[rbase + row];
        bool own = (tgt >= c0) && (tgt < c0 + 3);
        float lt = (tgt == c0) ? v0 : ((tgt == c0 + 1) ? v1 : v2);
        lacc += own ? (mx + __logf(s) - lt) : 0.f;
    }
    #pragma unroll
    for (int off = 16; off; off >>= 1) lacc += __shfl_xor_sync(0xffffffffu, lacc, off);
    if (tc == 0) atomicAdd(&g_loss, (double)lacc);

    // last finished block writes the mean loss (no extra kernel launch)
    if (write_loss) {
        __syncthreads();
        if (tid == 0) {
            __threadfence();
            unsigned old = atomicAdd(&g_cnt, 1u);
            if (old == gridDim.x - 1) {
                __threadfence();
                out[NLOGITS] = (float)(g_loss * (1.0 / (double)NROWS));
            }
        }
    }
}

// ---------------- launch ----------------------------------------------------
extern "C" void kernel_launch(void* const* d_in, const int* in_sizes, int n_in,
                              void* d_out, int out_size)
{
    const int*   idx     = (const int*)  d_in[0];
    const int*   targets = (const int*)  d_in[1];
    const float* emb     = (const float*)d_in[2];
    const float* W_ih    = (const float*)d_in[3];
    const float* W_hh    = (const float*)d_in[4];
    const float* b_ih    = (const float*)d_in[5];
    const float* b_hh    = (const float*)d_in[6];
    const float* fc_w    = (const float*)d_in[7];
    const float* fc_b    = (const float*)d_in[8];
    float* out = (float*)d_out;

    int write_loss = (out_size > NLOGITS) ? 1 : 0;

    prep_kernel<<<VV, 128>>>(emb, W_ih, W_hh, b_ih, b_hh);
    lstm_kernel<<<BB, 128>>>(idx);
    outproj_kernel<<<NROWS / 64, 256>>>(fc_w, fc_b, targets, out, write_loss);
}